// round 12
// baseline (speedup 1.0000x reference)
#include <cuda_runtime.h>
#include <cstdint>

// B=256, N=256. Greedy masked argmax (exact reference semantics: max value,
// tie -> smallest flat index). Keys = fp32 bits; softmax values in (0,1) =>
// positive, < 1.0f => order-monotone uint32, < 2^30.
// Packed slot: u64 = (key << 16) | (~((row<<8)|col) & 0xFFFF); u64 max ==
// lexicographic (max key, min flat index). key==0 => dead/invalid.
//
// One CTA per batch, 256 threads:
//   init : all 8 warps, per-row exact TOP-2 (coalesced float4, 4 REDUX/row):
//          head -> s_top, backup -> s_back. Warms L1 with the score matrix.
//   loop : warp 0 serial greedy loop. On head-hit: promote smem backup if its
//          key!=0 and col unmasked (exact: backup = max over unmasked-at-T
//          cols minus head col; masks only shrink). Else cooperative float4
//          rescan refilling BOTH head and backup. Warps 1-7 sleep at barrier.
//   epi  : all 8 warps fused zero+one-hot writeout (coalesced float4).

#define NN 256
#define FULL 0xFFFFFFFFu
typedef unsigned long long u64;

__device__ __forceinline__ u64 pairmax(u64 a, u64 b) { return a > b ? a : b; }

__device__ __forceinline__ u64 pack16(unsigned key, int row, unsigned col) {
    return ((u64)key << 16) | (u64)((~(unsigned)(((unsigned)row << 8) | col)) & 0xFFFFu);
}

// Per-lane top-2 over two float4 (cols 4*lane..+3 and 128+4*lane..+3) with
// per-lane mask words mwA/mwB, then warp-wide exact (top1, top2) via 4 REDUX.
__device__ __forceinline__ void top2_warp(float4 A, float4 Bq,
                                          unsigned mwA, unsigned mwB, int lane,
                                          unsigned& m1, unsigned& p1,
                                          unsigned& m2, unsigned& p2) {
    const int bit0 = 4 * (lane & 7);
    unsigned k1 = 0u, k2 = 0u; int c1 = 0, c2 = 0;
    float va[4] = {A.x, A.y, A.z, A.w};
    float vb[4] = {Bq.x, Bq.y, Bq.z, Bq.w};
    #pragma unroll
    for (int i = 0; i < 4; i++) {
        const unsigned key = ((mwA >> (bit0 + i)) & 1u) ? 0u : __float_as_uint(va[i]);
        const int col = 4 * lane + i;
        if (key > k1)      { k2 = k1; c2 = c1; k1 = key; c1 = col; }
        else if (key > k2) { k2 = key; c2 = col; }
    }
    #pragma unroll
    for (int i = 0; i < 4; i++) {
        const unsigned key = ((mwB >> (bit0 + i)) & 1u) ? 0u : __float_as_uint(vb[i]);
        const int col = 128 + 4 * lane + i;
        if (key > k1)      { k2 = k1; c2 = c1; k1 = key; c1 = col; }
        else if (key > k2) { k2 = key; c2 = col; }
    }
    m1 = __reduce_max_sync(FULL, k1);
    p1 = __reduce_min_sync(FULL, (k1 == m1) ? (unsigned)c1 : FULL);
    const bool win = (k1 == m1) && ((unsigned)c1 == p1);
    const unsigned sk = win ? k2 : k1;
    const unsigned sc = win ? (unsigned)c2 : (unsigned)c1;
    m2 = __reduce_max_sync(FULL, sk);
    p2 = __reduce_min_sync(FULL, (sk == m2) ? sc : FULL);
}

__global__ __launch_bounds__(256)
void greedy_perm_kernel(const float* __restrict__ scores, float* __restrict__ out) {
    __shared__ u64 s_top[NN];    // packed head per row
    __shared__ u64 s_back[NN];   // packed backup per row (key==0 => invalid)
    __shared__ int s_perm[NN];

    const int b    = blockIdx.x;
    const int tid  = threadIdx.x;
    const int warp = tid >> 5;
    const int lane = tid & 31;
    const float* base  = scores + (size_t)b * NN * NN;
    float*       obase = out    + (size_t)b * NN * NN;

    // ---------- parallel init: warp w -> rows w*32 .. w*32+31, exact top-2 ----------
    #pragma unroll 1
    for (int rg = 0; rg < 8; rg++) {
        const int row0 = warp * 32 + rg * 4;
        float4 A[4], Bq[4];
        #pragma unroll
        for (int q = 0; q < 4; q++) {
            const float4* rp = (const float4*)(base + (size_t)(row0 + q) * NN);
            A[q]  = __ldg(rp + lane);
            Bq[q] = __ldg(rp + 32 + lane);
        }
        #pragma unroll
        for (int q = 0; q < 4; q++) {
            const int row = row0 + q;
            unsigned m1, p1, m2, p2;
            top2_warp(A[q], Bq[q], 0u, 0u, lane, m1, p1, m2, p2);
            if (lane == 0) {
                s_top[row]  = pack16(m1, row, p1);
                s_back[row] = pack16(m2, row, p2);
            }
        }
    }
    __syncthreads();

    if (warp == 0) {
        // ---------- serial greedy loop ----------
        u64 h[8];
        unsigned cmask[8];
        #pragma unroll
        for (int k = 0; k < 8; k++) cmask[k] = 0u;
        #pragma unroll
        for (int j = 0; j < 8; j++) h[j] = s_top[j * 32 + lane];

        #pragma unroll 1
        for (int it = 0; it < NN; it++) {
            u64 loc = pairmax(pairmax(pairmax(h[0], h[1]), pairmax(h[2], h[3])),
                              pairmax(pairmax(h[4], h[5]), pairmax(h[6], h[7])));
            const unsigned bk = (unsigned)(loc >> 16);       // 30-bit key
            const unsigned cp = (~(unsigned)loc) & 0xFFFFu;  // (row<<8)|col

            const unsigned m   = __reduce_max_sync(FULL, bk);
            const unsigned sel = __reduce_min_sync(FULL, (bk == m) ? cp : FULL);
            const int r = (int)(sel >> 8);
            const int c = (int)(sel & 255u);

            if (lane == 0) s_perm[r] = c;

            // mask col c (replicated, static indexing)
            {
                const int w2 = c >> 5; const unsigned bit = 1u << (c & 31);
                #pragma unroll
                for (int k = 0; k < 8; k++) if (k == w2) cmask[k] |= bit;
            }
            // kill assigned row
            if (lane == (r & 31)) {
                const int slot = r >> 5;
                #pragma unroll
                for (int j = 0; j < 8; j++) if (j == slot) h[j] = 0ull;
            }

            if (it == NN - 1) break;

            // head-hit: promote smem backup if exact-valid, else mark rescan
            unsigned need = 0u;
            #pragma unroll
            for (int j = 0; j < 8; j++) {
                if ((unsigned)(h[j] >> 16) != 0u &&
                    (((~(unsigned)h[j]) & 255u) == (unsigned)c)) {
                    const int row = j * 32 + lane;
                    const u64 bb = s_back[row];
                    const unsigned bkk = (unsigned)(bb >> 16);
                    const unsigned bcc = (~(unsigned)bb) & 255u;
                    unsigned mw = 0u;
                    #pragma unroll
                    for (int k = 0; k < 8; k++)
                        if ((int)(bcc >> 5) == k) mw = cmask[k];
                    if (bkk != 0u && (((mw >> (bcc & 31)) & 1u) == 0u)) {
                        h[j] = bb;
                        s_back[row] = 0ull;   // consumed
                    } else {
                        need |= (1u << j);
                    }
                }
            }

            unsigned ln = __ballot_sync(FULL, need != 0u);
            while (ln) {
                const int src = __ffs(ln) - 1; ln &= ln - 1;
                unsigned em = __shfl_sync(FULL, need, src);
                while (em) {
                    const int jd = __ffs(em) - 1; em &= em - 1;
                    const int row = jd * 32 + src;
                    const float4* rp = (const float4*)(base + (size_t)row * NN);
                    const float4 A  = __ldg(rp + lane);
                    const float4 Bq = __ldg(rp + 32 + lane);
                    unsigned mwA = 0u, mwB = 0u;
                    #pragma unroll
                    for (int k = 0; k < 4; k++)
                        if ((lane >> 3) == k) { mwA = cmask[k]; mwB = cmask[k + 4]; }
                    unsigned m1, p1, m2, p2;
                    top2_warp(A, Bq, mwA, mwB, lane, m1, p1, m2, p2);
                    if (lane == src) {
                        const u64 nh = pack16(m1, row, p1);
                        #pragma unroll
                        for (int j = 0; j < 8; j++) if (j == jd) h[j] = nh;
                    }
                    if (lane == 0)
                        s_back[row] = (m2 != 0u) ? pack16(m2, row, p2) : 0ull;
                }
            }
        }
    }
    // warps 1-7 sleep at the barrier — zero contention during the loop.
    __syncthreads();

    // ---------- fused writeout: zeros + one-hot, 8 warps, coalesced float4 ----------
    #pragma unroll 1
    for (int rr = 0; rr < 32; rr++) {
        const int row = warp * 32 + rr;
        const int pc = s_perm[row];  // broadcast LDS
        float4* op = (float4*)(obase + (size_t)row * NN);
        #pragma unroll
        for (int hh = 0; hh < 2; hh++) {
            const int f4 = lane + 32 * hh;
            const int c0 = 4 * f4;
            float4 vv;
            vv.x = (pc == c0 + 0) ? 1.0f : 0.0f;
            vv.y = (pc == c0 + 1) ? 1.0f : 0.0f;
            vv.z = (pc == c0 + 2) ? 1.0f : 0.0f;
            vv.w = (pc == c0 + 3) ? 1.0f : 0.0f;
            op[f4] = vv;
        }
    }
}

extern "C" void kernel_launch(void* const* d_in, const int* in_sizes, int n_in,
                              void* d_out, int out_size) {
    const float* soft = (const float*)d_in[0];
    float* out = (float*)d_out;
    greedy_perm_kernel<<<256, 256>>>(soft, out);
}

// round 13
// speedup vs baseline: 1.6111x; 1.6111x over previous
#include <cuda_runtime.h>
#include <cstdint>

// B=256, N=256. Greedy masked argmax (exact reference semantics: max value,
// tie -> smallest flat index). Keys = fp32 bits; softmax values in (0,1) =>
// positive, < 1.0f => order-monotone uint32, < 2^30.
// Packed slot: u64 h = (key << 16) | (~((row<<8)|col) & 0xFFFF); u64 max ==
// lexicographic (max key, min flat index). 0 = dead.
//
// One CTA per batch, 256 threads:
//   init : all 8 warps, per-row argmax (coalesced float4, 2 REDUX/row) -> s_top
//   loop : ONE warp runs the serial greedy loop (R6/R11 winner body).
//          The greedy warp index is gw = (b + (b>>2)) & 3 — a batch-dependent
//          SMSP choice so the two co-resident CTAs on one SM (bids 148 apart;
//          148 % 4 == 0) put their serial warps on DIFFERENT SMSPs instead of
//          time-sharing one scheduler. Other warps sleep at the barrier.
//   epi  : all 8 warps fused zero+one-hot writeout (coalesced float4).

#define NN 256
#define FULL 0xFFFFFFFFu
typedef unsigned long long u64;

__device__ __forceinline__ u64 pairmax(u64 a, u64 b) { return a > b ? a : b; }

__global__ __launch_bounds__(256)
void greedy_perm_kernel(const float* __restrict__ scores, float* __restrict__ out) {
    __shared__ u64 s_top[NN];   // packed head per row
    __shared__ int s_perm[NN];

    const int b    = blockIdx.x;
    const int tid  = threadIdx.x;
    const int warp = tid >> 5;
    const int lane = tid & 31;
    const float* base  = scores + (size_t)b * NN * NN;
    float*       obase = out    + (size_t)b * NN * NN;

    // ---------- parallel init: warp w -> rows w*32 .. w*32+31 ----------
    #pragma unroll 1
    for (int rg = 0; rg < 8; rg++) {
        const int row0 = warp * 32 + rg * 4;
        float4 A[4], Bq[4];
        #pragma unroll
        for (int q = 0; q < 4; q++) {
            const float4* rp = (const float4*)(base + (size_t)(row0 + q) * NN);
            A[q]  = __ldg(rp + lane);
            Bq[q] = __ldg(rp + 32 + lane);
        }
        #pragma unroll
        for (int q = 0; q < 4; q++) {
            const int row = row0 + q;
            const int c0 = 4 * lane;
            u64 w[8];
            w[0] = ((u64)__float_as_uint(A[q].x)  << 32) | (unsigned)~(c0 + 0);
            w[1] = ((u64)__float_as_uint(A[q].y)  << 32) | (unsigned)~(c0 + 1);
            w[2] = ((u64)__float_as_uint(A[q].z)  << 32) | (unsigned)~(c0 + 2);
            w[3] = ((u64)__float_as_uint(A[q].w)  << 32) | (unsigned)~(c0 + 3);
            w[4] = ((u64)__float_as_uint(Bq[q].x) << 32) | (unsigned)~(128 + c0 + 0);
            w[5] = ((u64)__float_as_uint(Bq[q].y) << 32) | (unsigned)~(128 + c0 + 1);
            w[6] = ((u64)__float_as_uint(Bq[q].z) << 32) | (unsigned)~(128 + c0 + 2);
            w[7] = ((u64)__float_as_uint(Bq[q].w) << 32) | (unsigned)~(128 + c0 + 3);
            u64 loc = pairmax(pairmax(pairmax(w[0], w[1]), pairmax(w[2], w[3])),
                              pairmax(pairmax(w[4], w[5]), pairmax(w[6], w[7])));
            const unsigned k1 = (unsigned)(loc >> 32);
            const unsigned c1 = (~(unsigned)loc) & 255u;
            const unsigned m1 = __reduce_max_sync(FULL, k1);
            const unsigned p1 = __reduce_min_sync(FULL, (k1 == m1) ? c1 : FULL);
            if (lane == 0)
                s_top[row] = ((u64)m1 << 16) |
                             (u64)((~(unsigned)((row << 8) | (int)p1)) & 0xFFFFu);
        }
    }
    __syncthreads();

    // batch-dependent SMSP for the serial warp: co-resident CTAs (bids 148
    // apart, 148%4==0) get different (b + b/4) mod 4 -> different schedulers.
    const int gw = (b + (b >> 2)) & 3;

    if (warp == gw) {
        // ---------- serial greedy loop (R6 winner body) ----------
        u64 h[8];
        unsigned cmask[8];
        #pragma unroll
        for (int k = 0; k < 8; k++) cmask[k] = 0u;
        #pragma unroll
        for (int j = 0; j < 8; j++) h[j] = s_top[j * 32 + lane];

        #pragma unroll 1
        for (int it = 0; it < NN; it++) {
            u64 loc = pairmax(pairmax(pairmax(h[0], h[1]), pairmax(h[2], h[3])),
                              pairmax(pairmax(h[4], h[5]), pairmax(h[6], h[7])));
            const unsigned bk = (unsigned)(loc >> 16);       // 30-bit key
            const unsigned cp = (~(unsigned)loc) & 0xFFFFu;  // (row<<8)|col

            const unsigned m   = __reduce_max_sync(FULL, bk);
            const unsigned sel = __reduce_min_sync(FULL, (bk == m) ? cp : FULL);
            const int r = (int)(sel >> 8);
            const int c = (int)(sel & 255u);

            if (lane == 0) s_perm[r] = c;

            // mask col c (replicated, static indexing)
            {
                const int w2 = c >> 5; const unsigned bit = 1u << (c & 31);
                #pragma unroll
                for (int k = 0; k < 8; k++) if (k == w2) cmask[k] |= bit;
            }
            // kill assigned row
            if (lane == (r & 31)) {
                const int slot = r >> 5;
                #pragma unroll
                for (int j = 0; j < 8; j++) if (j == slot) h[j] = 0ull;
            }

            if (it == NN - 1) break;

            // rows whose cached argmax col just got masked -> eager rescan
            unsigned need = 0u;
            #pragma unroll
            for (int j = 0; j < 8; j++)
                if ((unsigned)(h[j] >> 16) != 0u &&
                    (((~(unsigned)h[j]) & 255u) == (unsigned)c))
                    need |= (1u << j);

            unsigned ln = __ballot_sync(FULL, need != 0u);
            while (ln) {
                const int src = __ffs(ln) - 1; ln &= ln - 1;
                unsigned em = __shfl_sync(FULL, need, src);
                while (em) {
                    const int jd = __ffs(em) - 1; em &= em - 1;
                    const int row = jd * 32 + src;
                    const float* rp = base + (size_t)row * NN;
                    u64 w[8];
                    #pragma unroll
                    for (int k = 0; k < 8; k++) {
                        const float v = __ldg(rp + k * 32 + lane);
                        const unsigned key =
                            ((cmask[k] >> lane) & 1u) ? 0u : __float_as_uint(v);
                        w[k] = ((u64)key << 32) | (unsigned)~(unsigned)(k * 32 + lane);
                    }
                    u64 lq = pairmax(pairmax(pairmax(w[0], w[1]), pairmax(w[2], w[3])),
                                     pairmax(pairmax(w[4], w[5]), pairmax(w[6], w[7])));
                    const unsigned kk = (unsigned)(lq >> 32);
                    const unsigned cc = (~(unsigned)lq) & 255u;
                    const unsigned mm = __reduce_max_sync(FULL, kk);
                    const unsigned pc = __reduce_min_sync(FULL, (kk == mm) ? cc : FULL);
                    if (lane == src) {
                        const u64 nh = ((u64)mm << 16) |
                            (u64)((~(unsigned)((row << 8) | (int)pc)) & 0xFFFFu);
                        #pragma unroll
                        for (int j = 0; j < 8; j++) if (j == jd) h[j] = nh;
                    }
                }
            }
        }
    }
    // other warps arrive immediately and sleep (deferred block) — no issue
    // pressure, no memory traffic during the serial loop.
    __syncthreads();

    // ---------- fused writeout: zeros + one-hot, 8 warps, coalesced float4 ----------
    #pragma unroll 1
    for (int rr = 0; rr < 32; rr++) {
        const int row = warp * 32 + rr;
        const int pc = s_perm[row];  // broadcast LDS
        float4* op = (float4*)(obase + (size_t)row * NN);
        #pragma unroll
        for (int hh = 0; hh < 2; hh++) {
            const int f4 = lane + 32 * hh;
            const int c0 = 4 * f4;
            float4 vv;
            vv.x = (pc == c0 + 0) ? 1.0f : 0.0f;
            vv.y = (pc == c0 + 1) ? 1.0f : 0.0f;
            vv.z = (pc == c0 + 2) ? 1.0f : 0.0f;
            vv.w = (pc == c0 + 3) ? 1.0f : 0.0f;
            op[f4] = vv;
        }
    }
}

extern "C" void kernel_launch(void* const* d_in, const int* in_sizes, int n_in,
                              void* d_out, int out_size) {
    const float* soft = (const float*)d_in[0];
    float* out = (float*)d_out;
    greedy_perm_kernel<<<256, 256>>>(soft, out);
}